// round 1
// baseline (speedup 1.0000x reference)
#include <cuda_runtime.h>
#include <cuda_bf16.h>
#include <math.h>

// ---------------- problem constants ----------------
#define B_SZ     2
#define L_SZ     1024
#define DMODEL   2048
#define DINNER   4096
#define DSTATE   16
#define DCONV    4
#define DTRANK   128
#define XDBL_K   (DTRANK + 2*DSTATE)   // 160
#define NROWS    (B_SZ * L_SZ)          // 2048

// ---------------- scratch (__device__ globals, no allocation) ----------------
__device__ float g_xz   [(size_t)NROWS * 2 * DINNER];   // [row][8192]  (x | z)
__device__ float g_xconv[(size_t)NROWS * DINNER];       // [row][4096]
__device__ float g_xdbl [(size_t)NROWS * XDBL_K];       // [row][160]   (dt|B|C)
__device__ float g_delta[(size_t)NROWS * DINNER];       // [row][4096]
__device__ float g_y    [(size_t)NROWS * DINNER];       // [row][4096]
__device__ float g_ybar [(size_t)NROWS * DINNER];       // [row][4096]

// ---------------- generic SGEMM: C[M,N] = A[M,K] * B[N,K]^T ----------------
// ACT==0: plain.  ACT==1: C = softplus(dot + bias[n])
#define BM 128
#define BN 128
#define BK 16

template<int ACT>
__global__ __launch_bounds__(256, 2)
void gemm_atb(const float* __restrict__ A, int lda,
              const float* __restrict__ B, int ldb,
              float* __restrict__ C, int ldc,
              int M, int N, int K,
              const float* __restrict__ bias)
{
    __shared__ float As[BK][BM];
    __shared__ float Bs[BK][BN];

    const int t  = threadIdx.x;      // 0..255
    const int tx = t & 15;
    const int ty = t >> 4;
    const int m0 = blockIdx.y * BM;
    const int n0 = blockIdx.x * BN;

    float acc[8][8];
    #pragma unroll
    for (int i = 0; i < 8; i++)
        #pragma unroll
        for (int j = 0; j < 8; j++) acc[i][j] = 0.f;

    for (int k0 = 0; k0 < K; k0 += BK) {
        // A tile (BM x BK) -> As[k][m]   (M,K assumed multiples of tile)
        #pragma unroll
        for (int q = 0; q < 2; q++) {
            int e4 = t * 2 + q;          // 0..511 float4 slots
            int m  = e4 >> 2;            // 0..127
            int kk = (e4 & 3) << 2;      // 0,4,8,12
            float4 v = *(const float4*)(A + (size_t)(m0 + m) * lda + k0 + kk);
            As[kk+0][m] = v.x; As[kk+1][m] = v.y;
            As[kk+2][m] = v.z; As[kk+3][m] = v.w;
        }
        // B tile (BN x BK) -> Bs[k][n], guard N edge
        #pragma unroll
        for (int q = 0; q < 2; q++) {
            int e4 = t * 2 + q;
            int n  = e4 >> 2;
            int kk = (e4 & 3) << 2;
            float4 v = make_float4(0.f, 0.f, 0.f, 0.f);
            if (n0 + n < N)
                v = *(const float4*)(B + (size_t)(n0 + n) * ldb + k0 + kk);
            Bs[kk+0][n] = v.x; Bs[kk+1][n] = v.y;
            Bs[kk+2][n] = v.z; Bs[kk+3][n] = v.w;
        }
        __syncthreads();

        #pragma unroll
        for (int kk = 0; kk < BK; kk++) {
            float ra[8], rb[8];
            #pragma unroll
            for (int i = 0; i < 8; i++) ra[i] = As[kk][ty * 8 + i];
            #pragma unroll
            for (int j = 0; j < 8; j++) rb[j] = Bs[kk][tx * 8 + j];
            #pragma unroll
            for (int i = 0; i < 8; i++)
                #pragma unroll
                for (int j = 0; j < 8; j++)
                    acc[i][j] = fmaf(ra[i], rb[j], acc[i][j]);
        }
        __syncthreads();
    }

    #pragma unroll
    for (int i = 0; i < 8; i++) {
        int m = m0 + ty * 8 + i;
        #pragma unroll
        for (int j = 0; j < 8; j++) {
            int n = n0 + tx * 8 + j;
            if (n < N) {
                float v = acc[i][j];
                if (ACT == 1) {
                    v += bias[n];
                    v = (v > 20.f) ? v : log1pf(expf(v));   // softplus
                }
                C[(size_t)m * ldc + n] = v;
            }
        }
    }
}

// ---------------- depthwise causal conv1d + bias + SiLU ----------------
__global__ void conv_silu_kernel(const float* __restrict__ xz,
                                 const float* __restrict__ cw,
                                 const float* __restrict__ cb,
                                 float* __restrict__ xc)
{
    int i = blockIdx.x * blockDim.x + threadIdx.x;   // over NROWS*DINNER
    int d = i & (DINNER - 1);
    int bl = i >> 12;                                // b*L + l
    int l = bl & (L_SZ - 1);
    int b = bl >> 10;

    float acc = cb[d];
    #pragma unroll
    for (int j = 0; j < DCONV; j++) {
        int l2 = l - (DCONV - 1) + j;
        if (l2 >= 0)
            acc = fmaf(xz[((size_t)(b * L_SZ + l2)) * (2 * DINNER) + d],
                       cw[d * DCONV + j], acc);
    }
    // silu
    xc[i] = acc / (1.f + expf(-acc));
}

// ---------------- selective scan: one 16-lane group per (b,d) channel ----------------
__global__ void scan_kernel(const float* __restrict__ delta,
                            const float* __restrict__ xdbl,
                            const float* __restrict__ xconv,
                            const float* __restrict__ A_log,
                            float* __restrict__ y)
{
    int n   = threadIdx.x & 15;                                     // state idx
    int grp = (blockIdx.x * blockDim.x + threadIdx.x) >> 4;        // channel 0..8191
    int b   = grp >> 12;
    int d   = grp & (DINNER - 1);

    float a = -expf(A_log[d * DSTATE + n]);
    float h = 0.f;
    size_t base = (size_t)b * L_SZ;

    for (int l = 0; l < L_SZ; l++) {
        size_t r = base + l;
        float dv = delta[r * DINNER + d];
        float xv = xconv[r * DINNER + d];
        float Bv = xdbl[r * XDBL_K + DTRANK + n];
        float Cv = xdbl[r * XDBL_K + DTRANK + DSTATE + n];

        float dA = __expf(dv * a);
        h = fmaf(h, dA, dv * Bv * xv);

        float p = h * Cv;
        p += __shfl_xor_sync(0xffffffffu, p, 8, 16);
        p += __shfl_xor_sync(0xffffffffu, p, 4, 16);
        p += __shfl_xor_sync(0xffffffffu, p, 2, 16);
        p += __shfl_xor_sync(0xffffffffu, p, 1, 16);
        if (n == 0) y[r * DINNER + d] = p;
    }
}

// ---------------- y = (y + x*D) * silu(z) ----------------
__global__ void ymod_kernel(const float* __restrict__ y,
                            const float* __restrict__ xconv,
                            const float* __restrict__ Dv,
                            const float* __restrict__ xz,
                            float* __restrict__ ybar)
{
    int i = blockIdx.x * blockDim.x + threadIdx.x;   // over NROWS*DINNER
    int d = i & (DINNER - 1);
    int r = i >> 12;
    float z = xz[(size_t)r * (2 * DINNER) + DINNER + d];
    float sz = z / (1.f + expf(-z));
    ybar[i] = (y[i] + xconv[i] * Dv[d]) * sz;
}

// ---------------- launch ----------------
extern "C" void kernel_launch(void* const* d_in, const int* in_sizes, int n_in,
                              void* d_out, int out_size)
{
    const float* hidden     = (const float*)d_in[0];
    const float* in_proj_w  = (const float*)d_in[1];
    const float* conv_w     = (const float*)d_in[2];
    const float* conv_b     = (const float*)d_in[3];
    const float* x_proj_w   = (const float*)d_in[4];
    const float* dt_proj_w  = (const float*)d_in[5];
    const float* dt_proj_b  = (const float*)d_in[6];
    const float* A_log      = (const float*)d_in[7];
    const float* Dvec       = (const float*)d_in[8];
    const float* out_proj_w = (const float*)d_in[9];
    float* out = (float*)d_out;

    float *xz, *xconv, *xdbl, *delta, *y, *ybar;
    cudaGetSymbolAddress((void**)&xz,    g_xz);
    cudaGetSymbolAddress((void**)&xconv, g_xconv);
    cudaGetSymbolAddress((void**)&xdbl,  g_xdbl);
    cudaGetSymbolAddress((void**)&delta, g_delta);
    cudaGetSymbolAddress((void**)&y,     g_y);
    cudaGetSymbolAddress((void**)&ybar,  g_ybar);

    // 1) xz = hidden @ in_proj_w^T   : [2048 x 2048] x [8192 x 2048]^T
    gemm_atb<0><<<dim3(2 * DINNER / BN, NROWS / BM), 256>>>(
        hidden, DMODEL, in_proj_w, DMODEL, xz, 2 * DINNER,
        NROWS, 2 * DINNER, DMODEL, nullptr);

    // 2) causal depthwise conv + silu
    conv_silu_kernel<<<(NROWS * DINNER) / 256, 256>>>(xz, conv_w, conv_b, xconv);

    // 3) x_dbl = xconv @ x_proj_w^T : [2048 x 4096] x [160 x 4096]^T
    gemm_atb<0><<<dim3((XDBL_K + BN - 1) / BN, NROWS / BM), 256>>>(
        xconv, DINNER, x_proj_w, DINNER, xdbl, XDBL_K,
        NROWS, XDBL_K, DINNER, nullptr);

    // 4) delta = softplus(dt_lo @ dt_proj_w^T + dt_proj_b) : [2048 x 128] x [4096 x 128]^T
    gemm_atb<1><<<dim3(DINNER / BN, NROWS / BM), 256>>>(
        xdbl, XDBL_K, dt_proj_w, DTRANK, delta, DINNER,
        NROWS, DINNER, DTRANK, dt_proj_b);

    // 5) selective scan
    scan_kernel<<<(B_SZ * DINNER * DSTATE) / 256, 256>>>(delta, xdbl, xconv, A_log, y);

    // 6) gating elementwise
    ymod_kernel<<<(NROWS * DINNER) / 256, 256>>>(y, xconv, Dvec, xz, ybar);

    // 7) out = ybar @ out_proj_w^T : [2048 x 4096] x [2048 x 4096]^T
    gemm_atb<0><<<dim3(DMODEL / BN, NROWS / BM), 256>>>(
        ybar, DINNER, out_proj_w, DINNER, out, DMODEL,
        NROWS, DMODEL, DINNER, nullptr);
}

// round 3
// speedup vs baseline: 2.2603x; 2.2603x over previous
#include <cuda_runtime.h>
#include <cuda_bf16.h>
#include <math.h>
#include <stdint.h>

// ---------------- problem constants ----------------
#define B_SZ     2
#define L_SZ     1024
#define DMODEL   2048
#define DINNER   4096
#define DSTATE   16
#define DCONV    4
#define DTRANK   128
#define XDBL_K   160
#define NROWS    2048

// extended-K (hi/lo-split bf16) sizes
#define KE_IN    (3*DMODEL)    // 6144
#define KE_X     (3*DINNER)    // 12288
#define KE_DT    (3*DTRANK)    // 384
#define KE_OUT   (3*DINNER)    // 12288

// ---------------- scratch (__device__ globals, no allocation) ----------------
__device__ float g_xz   [(size_t)NROWS * 2 * DINNER];
__device__ float g_xconv[(size_t)NROWS * DINNER];
__device__ float g_xdbl [(size_t)NROWS * XDBL_K];
__device__ float g_delta[(size_t)NROWS * DINNER];
__device__ float g_y    [(size_t)NROWS * DINNER];
__device__ float g_ybar [(size_t)NROWS * DINNER];

__device__ __align__(16) __nv_bfloat16 g_hid_e [(size_t)NROWS    * KE_IN ];
__device__ __align__(16) __nv_bfloat16 g_win_e [(size_t)2*DINNER * KE_IN ];
__device__ __align__(16) __nv_bfloat16 g_xc_e  [(size_t)NROWS    * KE_X  ];
__device__ __align__(16) __nv_bfloat16 g_xw_e  [(size_t)256      * KE_X  ];
__device__ __align__(16) __nv_bfloat16 g_dtlo_e[(size_t)NROWS    * KE_DT ];
__device__ __align__(16) __nv_bfloat16 g_dtw_e [(size_t)DINNER   * KE_DT ];
__device__ __align__(16) __nv_bfloat16 g_yb_e  [(size_t)NROWS    * KE_OUT];
__device__ __align__(16) __nv_bfloat16 g_ow_e  [(size_t)DMODEL   * KE_OUT];

// ---------------- PTX helpers (baseline ISA only: sm_80+ mma.sync / cp.async) ----
__device__ __forceinline__ uint32_t smem_u32(const void* p) {
    uint32_t a;
    asm("{ .reg .u64 t; cvta.to.shared.u64 t, %1; cvt.u32.u64 %0, t; }"
        : "=r"(a) : "l"(p));
    return a;
}

#define CP_ASYNC16(sa, ga) \
    asm volatile("cp.async.cg.shared.global [%0], [%1], 16;" \
                 :: "r"(sa), "l"(ga) : "memory")
#define CP_COMMIT() asm volatile("cp.async.commit_group;" ::: "memory")
#define CP_WAIT(N)  asm volatile("cp.async.wait_group %0;" :: "n"(N) : "memory")

#define LDSM_X4(R0, R1, R2, R3, ADDR) \
    asm volatile("ldmatrix.sync.aligned.m8n8.x4.shared.b16 {%0,%1,%2,%3}, [%4];" \
                 : "=r"(R0), "=r"(R1), "=r"(R2), "=r"(R3) : "r"(ADDR))

#define MMA16816(C, A0, A1, A2, A3, B0, B1) \
    asm volatile("mma.sync.aligned.m16n8k16.row.col.f32.bf16.bf16.f32 " \
                 "{%0,%1,%2,%3}, {%4,%5,%6,%7}, {%8,%9}, {%0,%1,%2,%3};" \
                 : "+f"((C)[0]), "+f"((C)[1]), "+f"((C)[2]), "+f"((C)[3]) \
                 : "r"(A0), "r"(A1), "r"(A2), "r"(A3), "r"(B0), "r"(B1))

// ---------------- HMMA GEMM: C[M,Nact] = A[M,Kext] * B[Nrows,Kext]^T --------
// block tile 128x128, BK=32, 4-stage cp.async pipeline, 8 warps (2x4),
// warp tile 64x32 = 4x4 m16n8k16 tiles. SMEM rows padded to 40 bf16 (80B).
#define BM 128
#define BN 128
#define BK 32
#define STAGES 4
#define LDS_ROW 40                      // bf16 per smem row (32 data + 8 pad)
#define TILE_BYTES (128 * LDS_ROW * 2)  // 10240 per operand per stage
#define STAGE_BYTES (2 * TILE_BYTES)    // 20480
#define GEMM_SMEM (STAGES * STAGE_BYTES) // 81920

template<int ACT>
__global__ void __launch_bounds__(256, 2)
gemm_mma(const __nv_bfloat16* __restrict__ A,
         const __nv_bfloat16* __restrict__ B,
         float* __restrict__ C, int ldc,
         int Nact, int Kext,
         const float* __restrict__ bias)
{
    extern __shared__ char smem[];
    const uint32_t sbase = smem_u32(smem);

    const int t    = threadIdx.x;
    const int lane = t & 31;
    const int wid  = t >> 5;
    const int wm   = wid >> 2;          // 0..1
    const int wn   = wid & 3;           // 0..3
    const int m0   = blockIdx.x * BM;
    const int n0   = blockIdx.y * BN;

    // ---- cp.async per-thread (2 chunks of 16B per operand) ----
    const int rowL0 = t >> 2,        cL0 = t & 3;
    const int rowL1 = (t + 256) >> 2, cL1 = (t + 256) & 3;
    const __nv_bfloat16* gA0 = A + (size_t)(m0 + rowL0) * Kext + cL0 * 8;
    const __nv_bfloat16* gA1 = A + (size_t)(m0 + rowL1) * Kext + cL1 * 8;
    const __nv_bfloat16* gB0 = B + (size_t)(n0 + rowL0) * Kext + cL0 * 8;
    const __nv_bfloat16* gB1 = B + (size_t)(n0 + rowL1) * Kext + cL1 * 8;
    const uint32_t sA0 = (uint32_t)(rowL0 * LDS_ROW * 2 + cL0 * 16);
    const uint32_t sA1 = (uint32_t)(rowL1 * LDS_ROW * 2 + cL1 * 16);

    // ---- ldmatrix per-thread lane addressing ----
    const int g = lane >> 3, r = lane & 7;
    const uint32_t a_off = (uint32_t)((wm * 64 + (g & 1) * 8 + r) * LDS_ROW * 2
                                      + ((g >> 1) * 8) * 2);
    const uint32_t b_off = (uint32_t)((wn * 32 + (g >> 1) * 8 + r) * LDS_ROW * 2
                                      + ((g & 1) * 8) * 2);

    float acc[4][4][4];
    #pragma unroll
    for (int i = 0; i < 4; i++)
        #pragma unroll
        for (int j = 0; j < 4; j++)
            #pragma unroll
            for (int e = 0; e < 4; e++) acc[i][j][e] = 0.f;

    const int iters = Kext / BK;

    // prologue: fill STAGES-1 stages
    #pragma unroll
    for (int s = 0; s < STAGES - 1; s++) {
        const size_t k0 = (size_t)s * BK;
        const uint32_t st = sbase + s * STAGE_BYTES;
        CP_ASYNC16(st + sA0, gA0 + k0);
        CP_ASYNC16(st + sA1, gA1 + k0);
        CP_ASYNC16(st + TILE_BYTES + sA0, gB0 + k0);
        CP_ASYNC16(st + TILE_BYTES + sA1, gB1 + k0);
        CP_COMMIT();
    }

    for (int it = 0; it < iters; it++) {
        CP_WAIT(STAGES - 2);
        __syncthreads();

        // issue load for stage it+STAGES-1 (slot consumed at iter it-1)
        if (it + STAGES - 1 < iters) {
            const size_t k0 = (size_t)(it + STAGES - 1) * BK;
            const uint32_t st = sbase + ((it + STAGES - 1) % STAGES) * STAGE_BYTES;
            CP_ASYNC16(st + sA0, gA0 + k0);
            CP_ASYNC16(st + sA1, gA1 + k0);
            CP_ASYNC16(st + TILE_BYTES + sA0, gB0 + k0);
            CP_ASYNC16(st + TILE_BYTES + sA1, gB1 + k0);
        }
        CP_COMMIT();

        // compute on stage it%STAGES
        const uint32_t sa = sbase + (it % STAGES) * STAGE_BYTES;
        const uint32_t sbb = sa + TILE_BYTES;
        #pragma unroll
        for (int ks = 0; ks < 2; ks++) {
            uint32_t af[4][4], bf2[2][4];
            #pragma unroll
            for (int i = 0; i < 4; i++)
                LDSM_X4(af[i][0], af[i][1], af[i][2], af[i][3],
                        sa + a_off + ks * 32 + i * (16 * LDS_ROW * 2));
            #pragma unroll
            for (int jp = 0; jp < 2; jp++)
                LDSM_X4(bf2[jp][0], bf2[jp][1], bf2[jp][2], bf2[jp][3],
                        sbb + b_off + ks * 32 + jp * (16 * LDS_ROW * 2));
            #pragma unroll
            for (int i = 0; i < 4; i++)
                #pragma unroll
                for (int j = 0; j < 4; j++)
                    MMA16816(acc[i][j], af[i][0], af[i][1], af[i][2], af[i][3],
                             bf2[j >> 1][(j & 1) * 2], bf2[j >> 1][(j & 1) * 2 + 1]);
        }
    }

    // ---- epilogue ----
    #pragma unroll
    for (int i = 0; i < 4; i++) {
        const int m = m0 + wm * 64 + i * 16 + (lane >> 2);
        #pragma unroll
        for (int j = 0; j < 4; j++) {
            const int n = n0 + wn * 32 + j * 8 + (lane & 3) * 2;
            #pragma unroll
            for (int e = 0; e < 4; e++) {
                const int mm = m + (e >> 1) * 8;
                const int nn = n + (e & 1);
                if (nn < Nact) {
                    float v = acc[i][j][e];
                    if (ACT == 1) {
                        v += bias[nn];
                        v = (v > 20.f) ? v : log1pf(expf(v));
                    }
                    C[(size_t)mm * ldc + nn] = v;
                }
            }
        }
    }
}

// ---------------- fp32 -> extended-K bf16 hi/lo conversion ----------------
// PAT 0 (A operand): [hi | lo | hi]   PAT 1 (B operand): [hi | hi | lo]
template<int PAT>
__global__ void cvt_ext(const float* __restrict__ in, int ldin, int Kin,
                        __nv_bfloat16* __restrict__ out, int R)
{
    int k = blockIdx.x * blockDim.x + threadIdx.x;
    int r = blockIdx.y;
    if (k >= Kin) return;
    float v = (r < R) ? in[(size_t)r * ldin + k] : 0.f;
    __nv_bfloat16 h = __float2bfloat16(v);
    __nv_bfloat16 l = __float2bfloat16(v - __bfloat162float(h));
    size_t o = (size_t)r * 3 * Kin;
    if (PAT == 0) { out[o + k] = h; out[o + Kin + k] = l; out[o + 2 * Kin + k] = h; }
    else          { out[o + k] = h; out[o + Kin + k] = h; out[o + 2 * Kin + k] = l; }
}

// ---------------- depthwise causal conv1d + bias + SiLU ----------------
__global__ void conv_silu_kernel(const float* __restrict__ xz,
                                 const float* __restrict__ cw,
                                 const float* __restrict__ cb,
                                 float* __restrict__ xc)
{
    int i = blockIdx.x * blockDim.x + threadIdx.x;
    int d = i & (DINNER - 1);
    int bl = i >> 12;
    int l = bl & (L_SZ - 1);
    int b = bl >> 10;

    float acc = cb[d];
    #pragma unroll
    for (int j = 0; j < DCONV; j++) {
        int l2 = l - (DCONV - 1) + j;
        if (l2 >= 0)
            acc = fmaf(xz[((size_t)(b * L_SZ + l2)) * (2 * DINNER) + d],
                       cw[d * DCONV + j], acc);
    }
    xc[i] = acc / (1.f + expf(-acc));
}

// ---------------- selective scan ----------------
__global__ void scan_kernel(const float* __restrict__ delta,
                            const float* __restrict__ xdbl,
                            const float* __restrict__ xconv,
                            const float* __restrict__ A_log,
                            float* __restrict__ y)
{
    int n   = threadIdx.x & 15;
    int grp = (blockIdx.x * blockDim.x + threadIdx.x) >> 4;
    int b   = grp >> 12;
    int d   = grp & (DINNER - 1);

    float a = -expf(A_log[d * DSTATE + n]);
    float h = 0.f;
    size_t base = (size_t)b * L_SZ;

    for (int l = 0; l < L_SZ; l++) {
        size_t r = base + l;
        float dv = delta[r * DINNER + d];
        float xv = xconv[r * DINNER + d];
        float Bv = xdbl[r * XDBL_K + DTRANK + n];
        float Cv = xdbl[r * XDBL_K + DTRANK + DSTATE + n];

        float dA = __expf(dv * a);
        h = fmaf(h, dA, dv * Bv * xv);

        float p = h * Cv;
        p += __shfl_xor_sync(0xffffffffu, p, 8, 16);
        p += __shfl_xor_sync(0xffffffffu, p, 4, 16);
        p += __shfl_xor_sync(0xffffffffu, p, 2, 16);
        p += __shfl_xor_sync(0xffffffffu, p, 1, 16);
        if (n == 0) y[r * DINNER + d] = p;
    }
}

// ---------------- y = (y + x*D) * silu(z) ----------------
__global__ void ymod_kernel(const float* __restrict__ y,
                            const float* __restrict__ xconv,
                            const float* __restrict__ Dv,
                            const float* __restrict__ xz,
                            float* __restrict__ ybar)
{
    int i = blockIdx.x * blockDim.x + threadIdx.x;
    int d = i & (DINNER - 1);
    int r = i >> 12;
    float z = xz[(size_t)r * (2 * DINNER) + DINNER + d];
    float sz = z / (1.f + expf(-z));
    ybar[i] = (y[i] + xconv[i] * Dv[d]) * sz;
}

// ---------------- launch ----------------
extern "C" void kernel_launch(void* const* d_in, const int* in_sizes, int n_in,
                              void* d_out, int out_size)
{
    const float* hidden     = (const float*)d_in[0];
    const float* in_proj_w  = (const float*)d_in[1];
    const float* conv_w     = (const float*)d_in[2];
    const float* conv_b     = (const float*)d_in[3];
    const float* x_proj_w   = (const float*)d_in[4];
    const float* dt_proj_w  = (const float*)d_in[5];
    const float* dt_proj_b  = (const float*)d_in[6];
    const float* A_log      = (const float*)d_in[7];
    const float* Dvec       = (const float*)d_in[8];
    const float* out_proj_w = (const float*)d_in[9];
    float* out = (float*)d_out;

    float *xz, *xconv, *xdbl, *delta, *y, *ybar;
    __nv_bfloat16 *hid_e, *win_e, *xc_e, *xw_e, *dtlo_e, *dtw_e, *yb_e, *ow_e;
    cudaGetSymbolAddress((void**)&xz,    g_xz);
    cudaGetSymbolAddress((void**)&xconv, g_xconv);
    cudaGetSymbolAddress((void**)&xdbl,  g_xdbl);
    cudaGetSymbolAddress((void**)&delta, g_delta);
    cudaGetSymbolAddress((void**)&y,     g_y);
    cudaGetSymbolAddress((void**)&ybar,  g_ybar);
    cudaGetSymbolAddress((void**)&hid_e, g_hid_e);
    cudaGetSymbolAddress((void**)&win_e, g_win_e);
    cudaGetSymbolAddress((void**)&xc_e,  g_xc_e);
    cudaGetSymbolAddress((void**)&xw_e,  g_xw_e);
    cudaGetSymbolAddress((void**)&dtlo_e,g_dtlo_e);
    cudaGetSymbolAddress((void**)&dtw_e, g_dtw_e);
    cudaGetSymbolAddress((void**)&yb_e,  g_yb_e);
    cudaGetSymbolAddress((void**)&ow_e,  g_ow_e);

    // idempotent, called every launch (no static guards)
    cudaFuncSetAttribute(gemm_mma<0>, cudaFuncAttributeMaxDynamicSharedMemorySize, GEMM_SMEM);
    cudaFuncSetAttribute(gemm_mma<1>, cudaFuncAttributeMaxDynamicSharedMemorySize, GEMM_SMEM);

    // 1) in_proj: xz[2048, 8192] = hidden_ext @ win_ext^T  (Kext=6144)
    cvt_ext<0><<<dim3(DMODEL / 256, NROWS), 256>>>(hidden, DMODEL, DMODEL, hid_e, NROWS);
    cvt_ext<1><<<dim3(DMODEL / 256, 2 * DINNER), 256>>>(in_proj_w, DMODEL, DMODEL, win_e, 2 * DINNER);
    gemm_mma<0><<<dim3(NROWS / BM, (2 * DINNER) / BN), 256, GEMM_SMEM>>>(
        hid_e, win_e, xz, 2 * DINNER, 2 * DINNER, KE_IN, nullptr);

    // 2) conv + silu
    conv_silu_kernel<<<(NROWS * DINNER) / 256, 256>>>(xz, conv_w, conv_b, xconv);

    // 3) x_proj: xdbl[2048, 160] = xconv_ext @ xw_ext^T  (Kext=12288, B padded to 256 rows)
    cvt_ext<0><<<dim3(DINNER / 256, NROWS), 256>>>(xconv, DINNER, DINNER, xc_e, NROWS);
    cvt_ext<1><<<dim3(DINNER / 256, 256), 256>>>(x_proj_w, DINNER, DINNER, xw_e, XDBL_K);
    gemm_mma<0><<<dim3(NROWS / BM, 2), 256, GEMM_SMEM>>>(
        xc_e, xw_e, xdbl, XDBL_K, XDBL_K, KE_X, nullptr);

    // 4) dt_proj: delta = softplus(dtlo_ext @ dtw_ext^T + bias)  (Kext=384)
    cvt_ext<0><<<dim3(1, NROWS), 256>>>(xdbl, XDBL_K, DTRANK, dtlo_e, NROWS);
    cvt_ext<1><<<dim3(1, DINNER), 256>>>(dt_proj_w, DTRANK, DTRANK, dtw_e, DINNER);
    gemm_mma<1><<<dim3(NROWS / BM, DINNER / BN), 256, GEMM_SMEM>>>(
        dtlo_e, dtw_e, delta, DINNER, DINNER, KE_DT, dt_proj_b);

    // 5) selective scan
    scan_kernel<<<(B_SZ * DINNER * DSTATE) / 256, 256>>>(delta, xdbl, xconv, A_log, y);

    // 6) gating elementwise
    ymod_kernel<<<(NROWS * DINNER) / 256, 256>>>(y, xconv, Dvec, xz, ybar);

    // 7) out_proj: out[2048, 2048] = ybar_ext @ ow_ext^T  (Kext=12288)
    cvt_ext<0><<<dim3(DINNER / 256, NROWS), 256>>>(ybar, DINNER, DINNER, yb_e, NROWS);
    cvt_ext<1><<<dim3(DINNER / 256, DMODEL), 256>>>(out_proj_w, DINNER, DINNER, ow_e, DMODEL);
    gemm_mma<0><<<dim3(NROWS / BM, DMODEL / BN), 256, GEMM_SMEM>>>(
        yb_e, ow_e, out, DMODEL, DMODEL, KE_OUT, nullptr);
}

// round 4
// speedup vs baseline: 2.2784x; 1.0080x over previous
#include <cuda_runtime.h>
#include <cuda_bf16.h>
#include <math.h>
#include <stdint.h>

// ---------------- problem constants ----------------
#define B_SZ     2
#define L_SZ     1024
#define DMODEL   2048
#define DINNER   4096
#define DSTATE   16
#define DCONV    4
#define DTRANK   128
#define XDBL_K   160
#define NROWS    2048

// extended-K (hi/lo-split bf16) sizes
#define KE_IN    (3*DMODEL)    // 6144
#define KE_X     (3*DINNER)    // 12288
#define KE_DT    (3*DTRANK)    // 384
#define KE_OUT   (3*DINNER)    // 12288

#define XSPLIT   8             // split-K factor for x_proj

// ---------------- scratch (__device__ globals, no allocation) ----------------
__device__ float g_xz   [(size_t)NROWS * 2 * DINNER];
__device__ float g_xconv[(size_t)NROWS * DINNER];
__device__ float g_xdbl [(size_t)NROWS * XDBL_K];
__device__ float g_xpart[(size_t)XSPLIT * NROWS * XDBL_K];
__device__ float g_delta[(size_t)NROWS * DINNER];
__device__ float g_y    [(size_t)NROWS * DINNER];
__device__ float g_ybar [(size_t)NROWS * DINNER];

__device__ __align__(16) __nv_bfloat16 g_hid_e [(size_t)NROWS    * KE_IN ];
__device__ __align__(16) __nv_bfloat16 g_win_e [(size_t)2*DINNER * KE_IN ];
__device__ __align__(16) __nv_bfloat16 g_xc_e  [(size_t)NROWS    * KE_X  ];
__device__ __align__(16) __nv_bfloat16 g_xw_e  [(size_t)256      * KE_X  ];
__device__ __align__(16) __nv_bfloat16 g_dtlo_e[(size_t)NROWS    * KE_DT ];
__device__ __align__(16) __nv_bfloat16 g_dtw_e [(size_t)DINNER   * KE_DT ];
__device__ __align__(16) __nv_bfloat16 g_yb_e  [(size_t)NROWS    * KE_OUT];
__device__ __align__(16) __nv_bfloat16 g_ow_e  [(size_t)DMODEL   * KE_OUT];

// ---------------- PTX helpers (baseline ISA: sm_80+ mma.sync / cp.async) ------
__device__ __forceinline__ uint32_t smem_u32(const void* p) {
    uint32_t a;
    asm("{ .reg .u64 t; cvta.to.shared.u64 t, %1; cvt.u32.u64 %0, t; }"
        : "=r"(a) : "l"(p));
    return a;
}

#define CP_ASYNC16(sa, ga) \
    asm volatile("cp.async.cg.shared.global [%0], [%1], 16;" \
                 :: "r"(sa), "l"(ga) : "memory")
#define CP_COMMIT() asm volatile("cp.async.commit_group;" ::: "memory")
#define CP_WAIT(N)  asm volatile("cp.async.wait_group %0;" :: "n"(N) : "memory")

#define LDSM_X4(R0, R1, R2, R3, ADDR) \
    asm volatile("ldmatrix.sync.aligned.m8n8.x4.shared.b16 {%0,%1,%2,%3}, [%4];" \
                 : "=r"(R0), "=r"(R1), "=r"(R2), "=r"(R3) : "r"(ADDR))

#define MMA16816(C, A0, A1, A2, A3, B0, B1) \
    asm volatile("mma.sync.aligned.m16n8k16.row.col.f32.bf16.bf16.f32 " \
                 "{%0,%1,%2,%3}, {%4,%5,%6,%7}, {%8,%9}, {%0,%1,%2,%3};" \
                 : "+f"((C)[0]), "+f"((C)[1]), "+f"((C)[2]), "+f"((C)[3]) \
                 : "r"(A0), "r"(A1), "r"(A2), "r"(A3), "r"(B0), "r"(B1))

// ---------------- HMMA GEMM: C[M,Nact] = A[M,Kext] * B[Nrows,Kext]^T --------
// block tile 128(M) x 256(N), BK=32, 4-stage cp.async, 8 warps (2x4),
// warp tile 64x64 = 4x8 m16n8k16. SMEM rows padded to 40 bf16 (80B).
// Optional split-K over blockIdx.z (kIters K-chunks per split, partial
// outputs at C + z*partStride).
#define BM 128
#define BN 256
#define BK 32
#define STAGES 4
#define LDS_ROW 40
#define A_TILE_BYTES (BM * LDS_ROW * 2)          // 10240
#define B_TILE_BYTES (BN * LDS_ROW * 2)          // 20480
#define STAGE_BYTES  (A_TILE_BYTES + B_TILE_BYTES) // 30720
#define GEMM_SMEM (STAGES * STAGE_BYTES)          // 122880

template<int ACT>
__global__ void __launch_bounds__(256, 1)
gemm_mma(const __nv_bfloat16* __restrict__ A,
         const __nv_bfloat16* __restrict__ B,
         float* __restrict__ C, int ldc,
         int Nact, int Kext, int kIters, size_t partStride,
         const float* __restrict__ bias)
{
    extern __shared__ char smem[];
    const uint32_t sbase = smem_u32(smem);

    const int t    = threadIdx.x;
    const int lane = t & 31;
    const int wid  = t >> 5;
    const int wm   = wid >> 2;          // 0..1
    const int wn   = wid & 3;           // 0..3
    const int m0   = blockIdx.x * BM;
    const int n0   = blockIdx.y * BN;
    const size_t kbase = (size_t)blockIdx.z * kIters * BK;
    C += (size_t)blockIdx.z * partStride;

    // ---- cp.async per-thread addresses ----
    // A: 512 16B-chunks (2/thread), B: 1024 chunks (4/thread)
    const int ra0 = t >> 2,          ca0 = t & 3;
    const int ra1 = (t + 256) >> 2,  ca1 = (t + 256) & 3;
    const __nv_bfloat16* gA0 = A + (size_t)(m0 + ra0) * Kext + kbase + ca0 * 8;
    const __nv_bfloat16* gA1 = A + (size_t)(m0 + ra1) * Kext + kbase + ca1 * 8;
    const uint32_t sAo0 = (uint32_t)(ra0 * LDS_ROW * 2 + ca0 * 16);
    const uint32_t sAo1 = (uint32_t)(ra1 * LDS_ROW * 2 + ca1 * 16);
    const __nv_bfloat16* gB[4];
    uint32_t sBo[4];
    #pragma unroll
    for (int q = 0; q < 4; q++) {
        int id = t + q * 256;
        int rr = id >> 2, cc = id & 3;
        gB[q]  = B + (size_t)(n0 + rr) * Kext + kbase + cc * 8;
        sBo[q] = (uint32_t)(rr * LDS_ROW * 2 + cc * 16);
    }

    // ---- ldmatrix lane addressing ----
    const int g = lane >> 3, r = lane & 7;
    const uint32_t a_off = (uint32_t)((wm * 64 + (g & 1) * 8 + r) * LDS_ROW * 2
                                      + ((g >> 1) * 8) * 2);
    const uint32_t b_off = (uint32_t)((wn * 64 + (g >> 1) * 8 + r) * LDS_ROW * 2
                                      + ((g & 1) * 8) * 2);

    float acc[4][8][4];
    #pragma unroll
    for (int i = 0; i < 4; i++)
        #pragma unroll
        for (int j = 0; j < 8; j++)
            #pragma unroll
            for (int e = 0; e < 4; e++) acc[i][j][e] = 0.f;

    // prologue
    #pragma unroll
    for (int s = 0; s < STAGES - 1; s++) {
        const size_t k0 = (size_t)s * BK;
        const uint32_t st = sbase + s * STAGE_BYTES;
        CP_ASYNC16(st + sAo0, gA0 + k0);
        CP_ASYNC16(st + sAo1, gA1 + k0);
        #pragma unroll
        for (int q = 0; q < 4; q++)
            CP_ASYNC16(st + A_TILE_BYTES + sBo[q], gB[q] + k0);
        CP_COMMIT();
    }

    for (int it = 0; it < kIters; it++) {
        CP_WAIT(STAGES - 2);
        __syncthreads();

        if (it + STAGES - 1 < kIters) {
            const size_t k0 = (size_t)(it + STAGES - 1) * BK;
            const uint32_t st = sbase + ((it + STAGES - 1) % STAGES) * STAGE_BYTES;
            CP_ASYNC16(st + sAo0, gA0 + k0);
            CP_ASYNC16(st + sAo1, gA1 + k0);
            #pragma unroll
            for (int q = 0; q < 4; q++)
                CP_ASYNC16(st + A_TILE_BYTES + sBo[q], gB[q] + k0);
        }
        CP_COMMIT();

        const uint32_t sa  = sbase + (it % STAGES) * STAGE_BYTES;
        const uint32_t sbb = sa + A_TILE_BYTES;
        #pragma unroll
        for (int ks = 0; ks < 2; ks++) {
            uint32_t af[4][4], bfr[4][4];
            #pragma unroll
            for (int i = 0; i < 4; i++)
                LDSM_X4(af[i][0], af[i][1], af[i][2], af[i][3],
                        sa + a_off + ks * 32 + i * (16 * LDS_ROW * 2));
            #pragma unroll
            for (int jp = 0; jp < 4; jp++)
                LDSM_X4(bfr[jp][0], bfr[jp][1], bfr[jp][2], bfr[jp][3],
                        sbb + b_off + ks * 32 + jp * (16 * LDS_ROW * 2));
            #pragma unroll
            for (int i = 0; i < 4; i++)
                #pragma unroll
                for (int j = 0; j < 8; j++)
                    MMA16816(acc[i][j], af[i][0], af[i][1], af[i][2], af[i][3],
                             bfr[j >> 1][(j & 1) * 2], bfr[j >> 1][(j & 1) * 2 + 1]);
        }
        __syncthreads();
    }

    // ---- epilogue ----
    #pragma unroll
    for (int i = 0; i < 4; i++) {
        const int m = m0 + wm * 64 + i * 16 + (lane >> 2);
        #pragma unroll
        for (int j = 0; j < 8; j++) {
            const int n = n0 + wn * 64 + j * 8 + (lane & 3) * 2;
            #pragma unroll
            for (int e = 0; e < 4; e++) {
                const int mm = m + (e >> 1) * 8;
                const int nn = n + (e & 1);
                if (nn < Nact) {
                    float v = acc[i][j][e];
                    if (ACT == 1) {
                        v += bias[nn];
                        v = (v > 20.f) ? v : log1pf(expf(v));
                    }
                    C[(size_t)mm * ldc + nn] = v;
                }
            }
        }
    }
}

// ---------------- split-K reduction for x_proj ----------------
__global__ void reduce_split(const float* __restrict__ part,
                             float* __restrict__ out, int n)
{
    int i = blockIdx.x * blockDim.x + threadIdx.x;
    if (i >= n) return;
    float s = 0.f;
    #pragma unroll
    for (int p = 0; p < XSPLIT; p++) s += part[(size_t)p * n + i];
    out[i] = s;
}

// ---------------- fp32 -> extended-K bf16 hi/lo conversion ----------------
// PAT 0 (A operand): [hi | lo | hi]   PAT 1 (B operand): [hi | hi | lo]
template<int PAT>
__global__ void cvt_ext(const float* __restrict__ in, int ldin, int Kin,
                        __nv_bfloat16* __restrict__ out, int R)
{
    int k = blockIdx.x * blockDim.x + threadIdx.x;
    int r = blockIdx.y;
    if (k >= Kin) return;
    float v = (r < R) ? in[(size_t)r * ldin + k] : 0.f;
    __nv_bfloat16 h = __float2bfloat16(v);
    __nv_bfloat16 l = __float2bfloat16(v - __bfloat162float(h));
    size_t o = (size_t)r * 3 * Kin;
    if (PAT == 0) { out[o + k] = h; out[o + Kin + k] = l; out[o + 2 * Kin + k] = h; }
    else          { out[o + k] = h; out[o + Kin + k] = h; out[o + 2 * Kin + k] = l; }
}

// ---------------- depthwise causal conv1d + bias + SiLU ----------------
__global__ void conv_silu_kernel(const float* __restrict__ xz,
                                 const float* __restrict__ cw,
                                 const float* __restrict__ cb,
                                 float* __restrict__ xc)
{
    int i = blockIdx.x * blockDim.x + threadIdx.x;
    int d = i & (DINNER - 1);
    int bl = i >> 12;
    int l = bl & (L_SZ - 1);
    int b = bl >> 10;

    float acc = cb[d];
    #pragma unroll
    for (int j = 0; j < DCONV; j++) {
        int l2 = l - (DCONV - 1) + j;
        if (l2 >= 0)
            acc = fmaf(xz[((size_t)(b * L_SZ + l2)) * (2 * DINNER) + d],
                       cw[d * DCONV + j], acc);
    }
    xc[i] = acc / (1.f + expf(-acc));
}

// ---------------- selective scan ----------------
__global__ void scan_kernel(const float* __restrict__ delta,
                            const float* __restrict__ xdbl,
                            const float* __restrict__ xconv,
                            const float* __restrict__ A_log,
                            float* __restrict__ y)
{
    int n   = threadIdx.x & 15;
    int grp = (blockIdx.x * blockDim.x + threadIdx.x) >> 4;
    int b   = grp >> 12;
    int d   = grp & (DINNER - 1);

    float a = -expf(A_log[d * DSTATE + n]);
    float h = 0.f;
    size_t base = (size_t)b * L_SZ;

    for (int l = 0; l < L_SZ; l++) {
        size_t r = base + l;
        float dv = delta[r * DINNER + d];
        float xv = xconv[r * DINNER + d];
        float Bv = xdbl[r * XDBL_K + DTRANK + n];
        float Cv = xdbl[r * XDBL_K + DTRANK + DSTATE + n];

        float dA = __expf(dv * a);
        h = fmaf(h, dA, dv * Bv * xv);

        float p = h * Cv;
        p += __shfl_xor_sync(0xffffffffu, p, 8, 16);
        p += __shfl_xor_sync(0xffffffffu, p, 4, 16);
        p += __shfl_xor_sync(0xffffffffu, p, 2, 16);
        p += __shfl_xor_sync(0xffffffffu, p, 1, 16);
        if (n == 0) y[r * DINNER + d] = p;
    }
}

// ---------------- y = (y + x*D) * silu(z) ----------------
__global__ void ymod_kernel(const float* __restrict__ y,
                            const float* __restrict__ xconv,
                            const float* __restrict__ Dv,
                            const float* __restrict__ xz,
                            float* __restrict__ ybar)
{
    int i = blockIdx.x * blockDim.x + threadIdx.x;
    int d = i & (DINNER - 1);
    int r = i >> 12;
    float z = xz[(size_t)r * (2 * DINNER) + DINNER + d];
    float sz = z / (1.f + expf(-z));
    ybar[i] = (y[i] + xconv[i] * Dv[d]) * sz;
}

// ---------------- launch ----------------
extern "C" void kernel_launch(void* const* d_in, const int* in_sizes, int n_in,
                              void* d_out, int out_size)
{
    const float* hidden     = (const float*)d_in[0];
    const float* in_proj_w  = (const float*)d_in[1];
    const float* conv_w     = (const float*)d_in[2];
    const float* conv_b     = (const float*)d_in[3];
    const float* x_proj_w   = (const float*)d_in[4];
    const float* dt_proj_w  = (const float*)d_in[5];
    const float* dt_proj_b  = (const float*)d_in[6];
    const float* A_log      = (const float*)d_in[7];
    const float* Dvec       = (const float*)d_in[8];
    const float* out_proj_w = (const float*)d_in[9];
    float* out = (float*)d_out;

    float *xz, *xconv, *xdbl, *xpart, *delta, *y, *ybar;
    __nv_bfloat16 *hid_e, *win_e, *xc_e, *xw_e, *dtlo_e, *dtw_e, *yb_e, *ow_e;
    cudaGetSymbolAddress((void**)&xz,    g_xz);
    cudaGetSymbolAddress((void**)&xconv, g_xconv);
    cudaGetSymbolAddress((void**)&xdbl,  g_xdbl);
    cudaGetSymbolAddress((void**)&xpart, g_xpart);
    cudaGetSymbolAddress((void**)&delta, g_delta);
    cudaGetSymbolAddress((void**)&y,     g_y);
    cudaGetSymbolAddress((void**)&ybar,  g_ybar);
    cudaGetSymbolAddress((void**)&hid_e, g_hid_e);
    cudaGetSymbolAddress((void**)&win_e, g_win_e);
    cudaGetSymbolAddress((void**)&xc_e,  g_xc_e);
    cudaGetSymbolAddress((void**)&xw_e,  g_xw_e);
    cudaGetSymbolAddress((void**)&dtlo_e,g_dtlo_e);
    cudaGetSymbolAddress((void**)&dtw_e, g_dtw_e);
    cudaGetSymbolAddress((void**)&yb_e,  g_yb_e);
    cudaGetSymbolAddress((void**)&ow_e,  g_ow_e);

    cudaFuncSetAttribute(gemm_mma<0>, cudaFuncAttributeMaxDynamicSharedMemorySize, GEMM_SMEM);
    cudaFuncSetAttribute(gemm_mma<1>, cudaFuncAttributeMaxDynamicSharedMemorySize, GEMM_SMEM);

    // 1) in_proj: xz[2048, 8192] = hidden_ext @ win_ext^T  (Kext=6144)
    cvt_ext<0><<<dim3(DMODEL / 256, NROWS), 256>>>(hidden, DMODEL, DMODEL, hid_e, NROWS);
    cvt_ext<1><<<dim3(DMODEL / 256, 2 * DINNER), 256>>>(in_proj_w, DMODEL, DMODEL, win_e, 2 * DINNER);
    gemm_mma<0><<<dim3(NROWS / BM, (2 * DINNER) / BN), 256, GEMM_SMEM>>>(
        hid_e, win_e, xz, 2 * DINNER, 2 * DINNER, KE_IN, KE_IN / BK, 0, nullptr);

    // 2) conv + silu
    conv_silu_kernel<<<(NROWS * DINNER) / 256, 256>>>(xz, conv_w, conv_b, xconv);

    // 3) x_proj split-K: partials over 8 K-slices, then reduce
    cvt_ext<0><<<dim3(DINNER / 256, NROWS), 256>>>(xconv, DINNER, DINNER, xc_e, NROWS);
    cvt_ext<1><<<dim3(DINNER / 256, 256), 256>>>(x_proj_w, DINNER, DINNER, xw_e, XDBL_K);
    gemm_mma<0><<<dim3(NROWS / BM, 1, XSPLIT), 256, GEMM_SMEM>>>(
        xc_e, xw_e, xpart, XDBL_K, XDBL_K, KE_X, KE_X / BK / XSPLIT,
        (size_t)NROWS * XDBL_K, nullptr);
    reduce_split<<<(NROWS * XDBL_K + 255) / 256, 256>>>(xpart, xdbl, NROWS * XDBL_K);

    // 4) dt_proj: delta = softplus(dtlo_ext @ dtw_ext^T + bias)  (Kext=384)
    cvt_ext<0><<<dim3(1, NROWS), 256>>>(xdbl, XDBL_K, DTRANK, dtlo_e, NROWS);
    cvt_ext<1><<<dim3(1, DINNER), 256>>>(dt_proj_w, DTRANK, DTRANK, dtw_e, DINNER);
    gemm_mma<1><<<dim3(NROWS / BM, DINNER / BN), 256, GEMM_SMEM>>>(
        dtlo_e, dtw_e, delta, DINNER, DINNER, KE_DT, KE_DT / BK, 0, dt_proj_b);

    // 5) selective scan
    scan_kernel<<<(B_SZ * DINNER * DSTATE) / 256, 256>>>(delta, xdbl, xconv, A_log, y);

    // 6) gating elementwise
    ymod_kernel<<<(NROWS * DINNER) / 256, 256>>>(y, xconv, Dvec, xz, ybar);

    // 7) out_proj: out[2048, 2048] = ybar_ext @ ow_ext^T  (Kext=12288)
    cvt_ext<0><<<dim3(DINNER / 256, NROWS), 256>>>(ybar, DINNER, DINNER, yb_e, NROWS);
    cvt_ext<1><<<dim3(DINNER / 256, DMODEL), 256>>>(out_proj_w, DINNER, DINNER, ow_e, DMODEL);
    gemm_mma<0><<<dim3(NROWS / BM, DMODEL / BN), 256, GEMM_SMEM>>>(
        yb_e, ow_e, out, DMODEL, DMODEL, KE_OUT, KE_OUT / BK, 0, nullptr);
}

// round 5
// speedup vs baseline: 2.9388x; 1.2899x over previous
#include <cuda_runtime.h>
#include <cuda_fp16.h>
#include <math.h>
#include <stdint.h>

// ---------------- problem constants ----------------
#define B_SZ     2
#define L_SZ     1024
#define DMODEL   2048
#define DINNER   4096
#define DSTATE   16
#define DCONV    4
#define DTRANK   128
#define XDBL_K   160
#define NROWS    2048

// extended-K sizes: 2-term fp16 hi/lo for big GEMMs, 3-term for small ones
#define KE_IN    (2*DMODEL)    // 4096
#define KE_X     (3*DINNER)    // 12288
#define KE_DT    (3*DTRANK)    // 384
#define KE_OUT   (2*DINNER)    // 8192

#define XSPLIT   8             // split-K factor for x_proj

// ---------------- scratch (__device__ globals, no allocation) ----------------
__device__ float g_xz   [(size_t)NROWS * 2 * DINNER];
__device__ float g_xconv[(size_t)NROWS * DINNER];
__device__ float g_xdbl [(size_t)NROWS * XDBL_K];
__device__ float g_xpart[(size_t)XSPLIT * NROWS * XDBL_K];
__device__ float g_delta[(size_t)NROWS * DINNER];
__device__ float g_y    [(size_t)NROWS * DINNER];
__device__ float g_ybar [(size_t)NROWS * DINNER];

__device__ __align__(16) __half g_hid_e [(size_t)NROWS    * KE_IN ];
__device__ __align__(16) __half g_win_e [(size_t)2*DINNER * KE_IN ];
__device__ __align__(16) __half g_xc_e  [(size_t)NROWS    * KE_X  ];
__device__ __align__(16) __half g_xw_e  [(size_t)256      * KE_X  ];
__device__ __align__(16) __half g_dtlo_e[(size_t)NROWS    * KE_DT ];
__device__ __align__(16) __half g_dtw_e [(size_t)DINNER   * KE_DT ];
__device__ __align__(16) __half g_yb_e  [(size_t)NROWS    * KE_OUT];
__device__ __align__(16) __half g_ow_e  [(size_t)DMODEL   * KE_OUT];

// ---------------- PTX helpers (baseline ISA: sm_80+ mma.sync / cp.async) ------
__device__ __forceinline__ uint32_t smem_u32(const void* p) {
    uint32_t a;
    asm("{ .reg .u64 t; cvta.to.shared.u64 t, %1; cvt.u32.u64 %0, t; }"
        : "=r"(a) : "l"(p));
    return a;
}

#define CP_ASYNC16(sa, ga) \
    asm volatile("cp.async.cg.shared.global [%0], [%1], 16;" \
                 :: "r"(sa), "l"(ga) : "memory")
#define CP_COMMIT() asm volatile("cp.async.commit_group;" ::: "memory")
#define CP_WAIT(N)  asm volatile("cp.async.wait_group %0;" :: "n"(N) : "memory")

#define LDSM_X4(R0, R1, R2, R3, ADDR) \
    asm volatile("ldmatrix.sync.aligned.m8n8.x4.shared.b16 {%0,%1,%2,%3}, [%4];" \
                 : "=r"(R0), "=r"(R1), "=r"(R2), "=r"(R3) : "r"(ADDR))

#define MMA16816(C, A0, A1, A2, A3, B0, B1) \
    asm volatile("mma.sync.aligned.m16n8k16.row.col.f32.f16.f16.f32 " \
                 "{%0,%1,%2,%3}, {%4,%5,%6,%7}, {%8,%9}, {%0,%1,%2,%3};" \
                 : "+f"((C)[0]), "+f"((C)[1]), "+f"((C)[2]), "+f"((C)[3]) \
                 : "r"(A0), "r"(A1), "r"(A2), "r"(A3), "r"(B0), "r"(B1))

// ---------------- HMMA GEMM: C[M,Nact] = A[M,Kext] * B[Nrows,Kext]^T --------
// block tile 128(M) x 256(N), BK=32, 4-stage cp.async, 8 warps (2x4),
// warp tile 64x64 = 4x8 m16n8k16. SMEM rows padded to 40 halves (80B).
// Optional split-K over blockIdx.z.
#define BM 128
#define BN 256
#define BK 32
#define STAGES 4
#define LDS_ROW 40
#define A_TILE_BYTES (BM * LDS_ROW * 2)            // 10240
#define B_TILE_BYTES (BN * LDS_ROW * 2)            // 20480
#define STAGE_BYTES  (A_TILE_BYTES + B_TILE_BYTES) // 30720
#define GEMM_SMEM (STAGES * STAGE_BYTES)           // 122880

template<int ACT>
__global__ void __launch_bounds__(256, 1)
gemm_mma(const __half* __restrict__ A,
         const __half* __restrict__ B,
         float* __restrict__ C, int ldc,
         int Nact, int Kext, int kIters, size_t partStride,
         const float* __restrict__ bias)
{
    extern __shared__ char smem[];
    const uint32_t sbase = smem_u32(smem);

    const int t    = threadIdx.x;
    const int lane = t & 31;
    const int wid  = t >> 5;
    const int wm   = wid >> 2;          // 0..1
    const int wn   = wid & 3;           // 0..3
    const int m0   = blockIdx.x * BM;
    const int n0   = blockIdx.y * BN;
    const size_t kbase = (size_t)blockIdx.z * kIters * BK;
    C += (size_t)blockIdx.z * partStride;

    // ---- cp.async per-thread addresses ----
    const int ra0 = t >> 2,          ca0 = t & 3;
    const int ra1 = (t + 256) >> 2,  ca1 = (t + 256) & 3;
    const __half* gA0 = A + (size_t)(m0 + ra0) * Kext + kbase + ca0 * 8;
    const __half* gA1 = A + (size_t)(m0 + ra1) * Kext + kbase + ca1 * 8;
    const uint32_t sAo0 = (uint32_t)(ra0 * LDS_ROW * 2 + ca0 * 16);
    const uint32_t sAo1 = (uint32_t)(ra1 * LDS_ROW * 2 + ca1 * 16);
    const __half* gB[4];
    uint32_t sBo[4];
    #pragma unroll
    for (int q = 0; q < 4; q++) {
        int id = t + q * 256;
        int rr = id >> 2, cc = id & 3;
        gB[q]  = B + (size_t)(n0 + rr) * Kext + kbase + cc * 8;
        sBo[q] = (uint32_t)(rr * LDS_ROW * 2 + cc * 16);
    }

    // ---- ldmatrix lane addressing ----
    const int g = lane >> 3, r = lane & 7;
    const uint32_t a_off = (uint32_t)((wm * 64 + (g & 1) * 8 + r) * LDS_ROW * 2
                                      + ((g >> 1) * 8) * 2);
    const uint32_t b_off = (uint32_t)((wn * 64 + (g >> 1) * 8 + r) * LDS_ROW * 2
                                      + ((g & 1) * 8) * 2);

    float acc[4][8][4];
    #pragma unroll
    for (int i = 0; i < 4; i++)
        #pragma unroll
        for (int j = 0; j < 8; j++)
            #pragma unroll
            for (int e = 0; e < 4; e++) acc[i][j][e] = 0.f;

    // prologue
    #pragma unroll
    for (int s = 0; s < STAGES - 1; s++) {
        const size_t k0 = (size_t)s * BK;
        const uint32_t st = sbase + s * STAGE_BYTES;
        CP_ASYNC16(st + sAo0, gA0 + k0);
        CP_ASYNC16(st + sAo1, gA1 + k0);
        #pragma unroll
        for (int q = 0; q < 4; q++)
            CP_ASYNC16(st + A_TILE_BYTES + sBo[q], gB[q] + k0);
        CP_COMMIT();
    }

    for (int it = 0; it < kIters; it++) {
        CP_WAIT(STAGES - 2);
        __syncthreads();

        if (it + STAGES - 1 < kIters) {
            const size_t k0 = (size_t)(it + STAGES - 1) * BK;
            const uint32_t st = sbase + ((it + STAGES - 1) % STAGES) * STAGE_BYTES;
            CP_ASYNC16(st + sAo0, gA0 + k0);
            CP_ASYNC16(st + sAo1, gA1 + k0);
            #pragma unroll
            for (int q = 0; q < 4; q++)
                CP_ASYNC16(st + A_TILE_BYTES + sBo[q], gB[q] + k0);
        }
        CP_COMMIT();

        const uint32_t sa  = sbase + (it % STAGES) * STAGE_BYTES;
        const uint32_t sbb = sa + A_TILE_BYTES;
        #pragma unroll
        for (int ks = 0; ks < 2; ks++) {
            uint32_t af[4][4], bfr[4][4];
            #pragma unroll
            for (int i = 0; i < 4; i++)
                LDSM_X4(af[i][0], af[i][1], af[i][2], af[i][3],
                        sa + a_off + ks * 32 + i * (16 * LDS_ROW * 2));
            #pragma unroll
            for (int jp = 0; jp < 4; jp++)
                LDSM_X4(bfr[jp][0], bfr[jp][1], bfr[jp][2], bfr[jp][3],
                        sbb + b_off + ks * 32 + jp * (16 * LDS_ROW * 2));
            #pragma unroll
            for (int i = 0; i < 4; i++)
                #pragma unroll
                for (int j = 0; j < 8; j++)
                    MMA16816(acc[i][j], af[i][0], af[i][1], af[i][2], af[i][3],
                             bfr[j >> 1][(j & 1) * 2], bfr[j >> 1][(j & 1) * 2 + 1]);
        }
        __syncthreads();
    }

    // ---- epilogue ----
    #pragma unroll
    for (int i = 0; i < 4; i++) {
        const int m = m0 + wm * 64 + i * 16 + (lane >> 2);
        #pragma unroll
        for (int j = 0; j < 8; j++) {
            const int n = n0 + wn * 64 + j * 8 + (lane & 3) * 2;
            #pragma unroll
            for (int e = 0; e < 4; e++) {
                const int mm = m + (e >> 1) * 8;
                const int nn = n + (e & 1);
                if (nn < Nact) {
                    float v = acc[i][j][e];
                    if (ACT == 1) {
                        v += bias[nn];
                        v = (v > 20.f) ? v : log1pf(expf(v));
                    }
                    C[(size_t)mm * ldc + nn] = v;
                }
            }
        }
    }
}

// ---------------- split-K reduction for x_proj ----------------
__global__ void reduce_split(const float* __restrict__ part,
                             float* __restrict__ out, int n)
{
    int i = blockIdx.x * blockDim.x + threadIdx.x;
    if (i >= n) return;
    float s = 0.f;
    #pragma unroll
    for (int p = 0; p < XSPLIT; p++) s += part[(size_t)p * n + i];
    out[i] = s;
}

// ---------------- fp32 -> extended-K fp16 hi/lo conversion ----------------
// PAT 0 (A,3-term): [hi|lo|hi]  PAT 1 (B,3-term): [hi|hi|lo]
// PAT 2 (A,2-term): [hi|lo]     PAT 3 (B,2-term): [hi|hi]
template<int PAT>
__global__ void cvt_ext(const float* __restrict__ in, int ldin, int Kin,
                        __half* __restrict__ out, int R)
{
    int k = blockIdx.x * blockDim.x + threadIdx.x;
    int r = blockIdx.y;
    if (k >= Kin) return;
    float v = (r < R) ? in[(size_t)r * ldin + k] : 0.f;
    __half h = __float2half(v);
    __half l = __float2half(v - __half2float(h));
    if (PAT == 0) {
        size_t o = (size_t)r * 3 * Kin;
        out[o + k] = h; out[o + Kin + k] = l; out[o + 2 * Kin + k] = h;
    } else if (PAT == 1) {
        size_t o = (size_t)r * 3 * Kin;
        out[o + k] = h; out[o + Kin + k] = h; out[o + 2 * Kin + k] = l;
    } else if (PAT == 2) {
        size_t o = (size_t)r * 2 * Kin;
        out[o + k] = h; out[o + Kin + k] = l;
    } else {
        size_t o = (size_t)r * 2 * Kin;
        out[o + k] = h; out[o + Kin + k] = h;
    }
}

// ---------------- depthwise causal conv1d + bias + SiLU ----------------
__global__ void conv_silu_kernel(const float* __restrict__ xz,
                                 const float* __restrict__ cw,
                                 const float* __restrict__ cb,
                                 float* __restrict__ xc)
{
    int i = blockIdx.x * blockDim.x + threadIdx.x;
    int d = i & (DINNER - 1);
    int bl = i >> 12;
    int l = bl & (L_SZ - 1);
    int b = bl >> 10;

    float acc = cb[d];
    #pragma unroll
    for (int j = 0; j < DCONV; j++) {
        int l2 = l - (DCONV - 1) + j;
        if (l2 >= 0)
            acc = fmaf(xz[((size_t)(b * L_SZ + l2)) * (2 * DINNER) + d],
                       cw[d * DCONV + j], acc);
    }
    xc[i] = acc / (1.f + expf(-acc));
}

// ---------------- selective scan ----------------
__global__ void scan_kernel(const float* __restrict__ delta,
                            const float* __restrict__ xdbl,
                            const float* __restrict__ xconv,
                            const float* __restrict__ A_log,
                            float* __restrict__ y)
{
    int n   = threadIdx.x & 15;
    int grp = (blockIdx.x * blockDim.x + threadIdx.x) >> 4;
    int b   = grp >> 12;
    int d   = grp & (DINNER - 1);

    float a = -expf(A_log[d * DSTATE + n]);
    float h = 0.f;
    size_t base = (size_t)b * L_SZ;

    for (int l = 0; l < L_SZ; l++) {
        size_t r = base + l;
        float dv = delta[r * DINNER + d];
        float xv = xconv[r * DINNER + d];
        float Bv = xdbl[r * XDBL_K + DTRANK + n];
        float Cv = xdbl[r * XDBL_K + DTRANK + DSTATE + n];

        float dA = __expf(dv * a);
        h = fmaf(h, dA, dv * Bv * xv);

        float p = h * Cv;
        p += __shfl_xor_sync(0xffffffffu, p, 8, 16);
        p += __shfl_xor_sync(0xffffffffu, p, 4, 16);
        p += __shfl_xor_sync(0xffffffffu, p, 2, 16);
        p += __shfl_xor_sync(0xffffffffu, p, 1, 16);
        if (n == 0) y[r * DINNER + d] = p;
    }
}

// ---------------- y = (y + x*D) * silu(z) ----------------
__global__ void ymod_kernel(const float* __restrict__ y,
                            const float* __restrict__ xconv,
                            const float* __restrict__ Dv,
                            const float* __restrict__ xz,
                            float* __restrict__ ybar)
{
    int i = blockIdx.x * blockDim.x + threadIdx.x;
    int d = i & (DINNER - 1);
    int r = i >> 12;
    float z = xz[(size_t)r * (2 * DINNER) + DINNER + d];
    float sz = z / (1.f + expf(-z));
    ybar[i] = (y[i] + xconv[i] * Dv[d]) * sz;
}

// ---------------- launch ----------------
extern "C" void kernel_launch(void* const* d_in, const int* in_sizes, int n_in,
                              void* d_out, int out_size)
{
    const float* hidden     = (const float*)d_in[0];
    const float* in_proj_w  = (const float*)d_in[1];
    const float* conv_w     = (const float*)d_in[2];
    const float* conv_b     = (const float*)d_in[3];
    const float* x_proj_w   = (const float*)d_in[4];
    const float* dt_proj_w  = (const float*)d_in[5];
    const float* dt_proj_b  = (const float*)d_in[6];
    const float* A_log      = (const float*)d_in[7];
    const float* Dvec       = (const float*)d_in[8];
    const float* out_proj_w = (const float*)d_in[9];
    float* out = (float*)d_out;

    float *xz, *xconv, *xdbl, *xpart, *delta, *y, *ybar;
    __half *hid_e, *win_e, *xc_e, *xw_e, *dtlo_e, *dtw_e, *yb_e, *ow_e;
    cudaGetSymbolAddress((void**)&xz,    g_xz);
    cudaGetSymbolAddress((void**)&xconv, g_xconv);
    cudaGetSymbolAddress((void**)&xdbl,  g_xdbl);
    cudaGetSymbolAddress((void**)&xpart, g_xpart);
    cudaGetSymbolAddress((void**)&delta, g_delta);
    cudaGetSymbolAddress((void**)&y,     g_y);
    cudaGetSymbolAddress((void**)&ybar,  g_ybar);
    cudaGetSymbolAddress((void**)&hid_e, g_hid_e);
    cudaGetSymbolAddress((void**)&win_e, g_win_e);
    cudaGetSymbolAddress((void**)&xc_e,  g_xc_e);
    cudaGetSymbolAddress((void**)&xw_e,  g_xw_e);
    cudaGetSymbolAddress((void**)&dtlo_e,g_dtlo_e);
    cudaGetSymbolAddress((void**)&dtw_e, g_dtw_e);
    cudaGetSymbolAddress((void**)&yb_e,  g_yb_e);
    cudaGetSymbolAddress((void**)&ow_e,  g_ow_e);

    cudaFuncSetAttribute(gemm_mma<0>, cudaFuncAttributeMaxDynamicSharedMemorySize, GEMM_SMEM);
    cudaFuncSetAttribute(gemm_mma<1>, cudaFuncAttributeMaxDynamicSharedMemorySize, GEMM_SMEM);

    // weight conversions first (independent) so the in_proj GEMM is the 6th
    // launch and gets captured by ncu (-s 5 -c 1).
    cvt_ext<3><<<dim3(DMODEL / 256, 2 * DINNER), 256>>>(in_proj_w, DMODEL, DMODEL, win_e, 2 * DINNER); // 1
    cvt_ext<1><<<dim3(DINNER / 256, 256), 256>>>(x_proj_w, DINNER, DINNER, xw_e, XDBL_K);              // 2
    cvt_ext<1><<<dim3(1, DINNER), 256>>>(dt_proj_w, DTRANK, DTRANK, dtw_e, DINNER);                    // 3
    cvt_ext<3><<<dim3(DINNER / 256, DMODEL), 256>>>(out_proj_w, DINNER, DINNER, ow_e, DMODEL);         // 4
    cvt_ext<2><<<dim3(DMODEL / 256, NROWS), 256>>>(hidden, DMODEL, DMODEL, hid_e, NROWS);              // 5

    // 6) in_proj: xz[2048, 8192] = hid_ext @ win_ext^T  (Kext=4096, 2-term)
    gemm_mma<0><<<dim3(NROWS / BM, (2 * DINNER) / BN), 256, GEMM_SMEM>>>(
        hid_e, win_e, xz, 2 * DINNER, 2 * DINNER, KE_IN, KE_IN / BK, 0, nullptr);

    // conv + silu
    conv_silu_kernel<<<(NROWS * DINNER) / 256, 256>>>(xz, conv_w, conv_b, xconv);

    // x_proj (3-term, split-K): partials over 8 K-slices, then reduce
    cvt_ext<0><<<dim3(DINNER / 256, NROWS), 256>>>(xconv, DINNER, DINNER, xc_e, NROWS);
    gemm_mma<0><<<dim3(NROWS / BM, 1, XSPLIT), 256, GEMM_SMEM>>>(
        xc_e, xw_e, xpart, XDBL_K, XDBL_K, KE_X, KE_X / BK / XSPLIT,
        (size_t)NROWS * XDBL_K, nullptr);
    reduce_split<<<(NROWS * XDBL_K + 255) / 256, 256>>>(xpart, xdbl, NROWS * XDBL_K);

    // dt_proj (3-term): delta = softplus(dtlo_ext @ dtw_ext^T + bias)
    cvt_ext<0><<<dim3(1, NROWS), 256>>>(xdbl, XDBL_K, DTRANK, dtlo_e, NROWS);
    gemm_mma<1><<<dim3(NROWS / BM, DINNER / BN), 256, GEMM_SMEM>>>(
        dtlo_e, dtw_e, delta, DINNER, DINNER, KE_DT, KE_DT / BK, 0, dt_proj_b);

    // selective scan
    scan_kernel<<<(B_SZ * DINNER * DSTATE) / 256, 256>>>(delta, xdbl, xconv, A_log, y);

    // gating elementwise
    ymod_kernel<<<(NROWS * DINNER) / 256, 256>>>(y, xconv, Dvec, xz, ybar);

    // out_proj (2-term): out[2048, 2048] = yb_ext @ ow_ext^T  (Kext=8192)
    cvt_ext<2><<<dim3(DINNER / 256, NROWS), 256>>>(ybar, DINNER, DINNER, yb_e, NROWS);
    gemm_mma<0><<<dim3(NROWS / BM, DMODEL / BN), 256, GEMM_SMEM>>>(
        yb_e, ow_e, out, DMODEL, DMODEL, KE_OUT, KE_OUT / BK, 0, nullptr);
}